// round 2
// baseline (speedup 1.0000x reference)
#include <cuda_runtime.h>
#include <math.h>

// Problem constants
#define BB 2
#define TS 2048
#define HH 16
#define DD 128
#define CC 2048
#define MMR (BB*TS)          // 4096 rows in the [b*t, c] view

// 1/sqrt(2048)  (reference scales by 1/sqrt(seq_len), folded into Q)
#define RSQT 0.022097086912079608f

// ---------------------------------------------------------------------------
// Device scratch (no cudaMalloc allowed)
// ---------------------------------------------------------------------------
__device__ float g_Q[(size_t)BB*HH*TS*DD];   // [b,h,t,d]
__device__ float g_K[(size_t)BB*HH*TS*DD];
__device__ float g_V[(size_t)BB*HH*TS*DD];
__device__ float g_AO[(size_t)MMR*CC];       // attention out, [b*t, h*d]
__device__ float g_cfac[TS*DD];              // cos(m)+sin(m)

// ---------------------------------------------------------------------------
// f32x2 packed helpers (FFMA2 path — only reachable via PTX)
// ---------------------------------------------------------------------------
__device__ __forceinline__ unsigned long long pack2(float x, float y) {
    unsigned long long r;
    asm("mov.b64 %0, {%1, %2};" : "=l"(r) : "f"(x), "f"(y));
    return r;
}
__device__ __forceinline__ void unpack2(unsigned long long v, float& x, float& y) {
    asm("mov.b64 {%0, %1}, %2;" : "=f"(x), "=f"(y) : "l"(v));
}
__device__ __forceinline__ void ffma2(unsigned long long& c, unsigned long long a,
                                      unsigned long long b) {
    asm("fma.rn.f32x2 %0, %1, %2, %0;" : "+l"(c) : "l"(a), "l"(b));
}
__device__ __forceinline__ void fmul2(unsigned long long& c, unsigned long long a) {
    asm("mul.rn.f32x2 %0, %0, %1;" : "+l"(c) : "l"(a));
}

// ---------------------------------------------------------------------------
// RoPE factor table: cfac[t][d] = cos(t*freq[d%64]) + sin(t*freq[d%64])
// ---------------------------------------------------------------------------
__global__ void cfac_kernel() {
    int t = blockIdx.x;
    int d = threadIdx.x;
    int j = d & 63;
    float ex = (float)(2 * j) / 128.0f;
    float freq = 1.0f / powf(10000.0f, ex);
    float m = (float)t * freq;
    g_cfac[t * DD + d] = cosf(m) + sinf(m);
}

// ---------------------------------------------------------------------------
// Tiled SGEMM, 128x128x8, double-buffered smem, 8x8 micro-tiles via fma.rn.f32x2.
// A [4096, 2048] row-major @ W [2048, 2048] row-major.
// mode 0: -> g_Q  (scaled by cfac * RSQT, scattered to [b,h,t,d])
// mode 1: -> g_K  (scaled by cfac,        scattered to [b,h,t,d])
// mode 2: -> g_V  (                       scattered to [b,h,t,d])
// mode 3: g_AO @ Wo -> Cout (plain row-major)
// ---------------------------------------------------------------------------
__global__ __launch_bounds__(256) void gemm_kernel(
    const float* __restrict__ A_in,
    const float* __restrict__ W0, const float* __restrict__ W1,
    const float* __restrict__ W2, const float* __restrict__ W3,
    float* __restrict__ Cout, int modeBase)
{
    const int mode = modeBase + (int)blockIdx.z;
    const float* A  = (mode == 3) ? g_AO : A_in;
    const float* Bw = (mode == 0) ? W0 : (mode == 1) ? W1 : (mode == 2) ? W2 : W3;

    __shared__ float As[2][8][128];  // [buf][k][m]
    __shared__ float Bs[2][8][128];  // [buf][k][n]

    const int K = CC, N = CC;
    const int tid = threadIdx.x;
    const int tx = tid & 15, ty = tid >> 4;
    const int bm = blockIdx.y, bn = blockIdx.x;

    unsigned long long acc[8][4];
#pragma unroll
    for (int i = 0; i < 8; i++)
#pragma unroll
        for (int j = 0; j < 4; j++) acc[i][j] = 0ULL;

    const int arow = tid >> 1;
    const int acol = (tid & 1) * 4;
    const int brow = tid >> 5;
    const int bcol = (tid & 31) * 4;
    const float* Aptr = A  + (size_t)(bm * 128 + arow) * K + acol;
    const float* Bptr = Bw + (size_t)brow * N + bn * 128 + bcol;

    // prime buffer 0
    {
        float4 av = *(const float4*)(Aptr);
        float4 bv = *(const float4*)(Bptr);
        As[0][acol + 0][arow] = av.x;
        As[0][acol + 1][arow] = av.y;
        As[0][acol + 2][arow] = av.z;
        As[0][acol + 3][arow] = av.w;
        *(float4*)&Bs[0][brow][bcol] = bv;
    }
    __syncthreads();

    int buf = 0;
    for (int k0 = 0; k0 < K; k0 += 8) {
        // prefetch next k-tile into the other buffer (no sync needed before
        // writing it — nobody reads it until the next __syncthreads)
        if (k0 + 8 < K) {
            float4 av = *(const float4*)(Aptr + k0 + 8);
            float4 bv = *(const float4*)(Bptr + (size_t)(k0 + 8) * N);
            int nb = buf ^ 1;
            As[nb][acol + 0][arow] = av.x;
            As[nb][acol + 1][arow] = av.y;
            As[nb][acol + 2][arow] = av.z;
            As[nb][acol + 3][arow] = av.w;
            *(float4*)&Bs[nb][brow][bcol] = bv;
        }
#pragma unroll
        for (int kk = 0; kk < 8; kk++) {
            float4 a0 = *(const float4*)&As[buf][kk][ty * 8];
            float4 a1 = *(const float4*)&As[buf][kk][ty * 8 + 4];
            ulonglong2 b0 = *(const ulonglong2*)&Bs[buf][kk][tx * 8];
            ulonglong2 b1 = *(const ulonglong2*)&Bs[buf][kk][tx * 8 + 4];
            float aa[8] = {a0.x, a0.y, a0.z, a0.w, a1.x, a1.y, a1.z, a1.w};
#pragma unroll
            for (int i = 0; i < 8; i++) {
                unsigned long long a2 = pack2(aa[i], aa[i]);
                ffma2(acc[i][0], a2, b0.x);
                ffma2(acc[i][1], a2, b0.y);
                ffma2(acc[i][2], a2, b1.x);
                ffma2(acc[i][3], a2, b1.y);
            }
        }
        buf ^= 1;
        __syncthreads();
    }

    float c[8][8];
#pragma unroll
    for (int i = 0; i < 8; i++)
#pragma unroll
        for (int j4 = 0; j4 < 4; j4++)
            unpack2(acc[i][j4], c[i][2 * j4], c[i][2 * j4 + 1]);

    const int grow0 = bm * 128 + ty * 8;
    const int gcol0 = bn * 128 + tx * 8;

    if (mode == 3) {
#pragma unroll
        for (int i = 0; i < 8; i++) {
            float4* p = (float4*)(Cout + (size_t)(grow0 + i) * N + gcol0);
            p[0] = make_float4(c[i][0], c[i][1], c[i][2], c[i][3]);
            p[1] = make_float4(c[i][4], c[i][5], c[i][6], c[i][7]);
        }
    } else {
        float* outb = (mode == 0) ? g_Q : (mode == 1) ? g_K : g_V;
#pragma unroll
        for (int i = 0; i < 8; i++) {
            int grow = grow0 + i;
            int b = grow >> 11;        // / 2048
            int t = grow & 2047;
            float sc0[8];
            if (mode == 2) {
#pragma unroll
                for (int j = 0; j < 8; j++) sc0[j] = 1.0f;
            } else {
                const float4* cf = (const float4*)&g_cfac[t * DD + tx * 8];
                float4 f0 = cf[0], f1 = cf[1];
                float s = (mode == 0) ? RSQT : 1.0f;
                sc0[0] = f0.x * s; sc0[1] = f0.y * s; sc0[2] = f0.z * s; sc0[3] = f0.w * s;
                sc0[4] = f1.x * s; sc0[5] = f1.y * s; sc0[6] = f1.z * s; sc0[7] = f1.w * s;
            }
            // h == bn (because D == 128 == tile width), d = tx*8 + j
            float* dst = outb + ((size_t)(b * HH + bn) * TS + t) * DD + tx * 8;
            ((float4*)dst)[0] = make_float4(c[i][0] * sc0[0], c[i][1] * sc0[1],
                                            c[i][2] * sc0[2], c[i][3] * sc0[3]);
            ((float4*)dst)[1] = make_float4(c[i][4] * sc0[4], c[i][5] * sc0[5],
                                            c[i][6] * sc0[6], c[i][7] * sc0[7]);
        }
    }
}

// ---------------------------------------------------------------------------
// Flash-style attention: one CTA handles 128 q-rows of one (b,h).
// smem: Qs [d][m] (64KB) | Ks [d][n] -> reused as Ps [k][m] (64KB) | Vs [k][e] (64KB)
// ---------------------------------------------------------------------------
#define ATT_SMEM (3 * 128 * 128 * 4)

__global__ __launch_bounds__(256, 1) void attn_kernel(const float* __restrict__ mask)
{
    extern __shared__ float smem[];
    float* Qs = smem;
    float* Ks = smem + 16384;
    float* Vs = smem + 32768;

    const int tid = threadIdx.x;
    const int tx = tid & 15, ty = tid >> 4;
    const int mblk = blockIdx.x;
    const int bh = blockIdx.y;
    const int b = bh >> 4, h = bh & 15;

    const float* Qg = g_Q + (size_t)bh * TS * DD + (size_t)mblk * 128 * DD;
    const float* Kg = g_K + (size_t)bh * TS * DD;
    const float* Vg = g_V + (size_t)bh * TS * DD;

    // load Q tile transposed: Qs[d][m]
#pragma unroll
    for (int it = 0; it < 16; it++) {
        int lin = it * 256 + tid;
        int row = lin >> 5;
        int c4 = (lin & 31) << 2;
        float4 v = *(const float4*)(Qg + row * DD + c4);
        Qs[(c4 + 0) * 128 + row] = v.x;
        Qs[(c4 + 1) * 128 + row] = v.y;
        Qs[(c4 + 2) * 128 + row] = v.z;
        Qs[(c4 + 3) * 128 + row] = v.w;
    }

    float mi[8], li[8];
#pragma unroll
    for (int i = 0; i < 8; i++) { mi[i] = __int_as_float(0xff800000u); li[i] = 0.0f; }
    unsigned long long o2[8][4];
#pragma unroll
    for (int i = 0; i < 8; i++)
#pragma unroll
        for (int j = 0; j < 4; j++) o2[i][j] = 0ULL;

    for (int kt = 0; kt < 16; kt++) {
        __syncthreads();   // previous tile's PV reads complete before overwrite
        // load K tile transposed into Ks, V tile direct into Vs
#pragma unroll
        for (int it = 0; it < 16; it++) {
            int lin = it * 256 + tid;
            int row = lin >> 5;
            int c4 = (lin & 31) << 2;
            float4 kv = *(const float4*)(Kg + (size_t)kt * 128 * DD + row * DD + c4);
            Ks[(c4 + 0) * 128 + row] = kv.x;
            Ks[(c4 + 1) * 128 + row] = kv.y;
            Ks[(c4 + 2) * 128 + row] = kv.z;
            Ks[(c4 + 3) * 128 + row] = kv.w;
            float4 vv = *(const float4*)(Vg + (size_t)kt * 128 * DD + row * DD + c4);
            *(float4*)&Vs[row * 128 + c4] = vv;
        }
        __syncthreads();

        // S = Q K^T  (sum over d)
        unsigned long long s2[8][4];
#pragma unroll
        for (int i = 0; i < 8; i++)
#pragma unroll
            for (int j = 0; j < 4; j++) s2[i][j] = 0ULL;

#pragma unroll 4
        for (int dk = 0; dk < 128; dk++) {
            float4 a0 = *(const float4*)&Qs[dk * 128 + ty * 8];
            float4 a1 = *(const float4*)&Qs[dk * 128 + ty * 8 + 4];
            ulonglong2 b0 = *(const ulonglong2*)&Ks[dk * 128 + tx * 8];
            ulonglong2 b1 = *(const ulonglong2*)&Ks[dk * 128 + tx * 8 + 4];
            float aa[8] = {a0.x, a0.y, a0.z, a0.w, a1.x, a1.y, a1.z, a1.w};
#pragma unroll
            for (int i = 0; i < 8; i++) {
                unsigned long long a2 = pack2(aa[i], aa[i]);
                ffma2(s2[i][0], a2, b0.x);
                ffma2(s2[i][1], a2, b0.y);
                ffma2(s2[i][2], a2, b1.x);
                ffma2(s2[i][3], a2, b1.y);
            }
        }

        float s[8][8];
#pragma unroll
        for (int i = 0; i < 8; i++)
#pragma unroll
            for (int j4 = 0; j4 < 4; j4++)
                unpack2(s2[i][j4], s[i][2 * j4], s[i][2 * j4 + 1]);

        // + attention mask (zeros in practice, but semantically required)
        const float* mrow = mask + ((size_t)b * TS + (size_t)(mblk * 128 + ty * 8)) * TS
                                 + (size_t)kt * 128 + tx * 8;
#pragma unroll
        for (int i = 0; i < 8; i++) {
            float4 m0 = *(const float4*)(mrow + (size_t)i * TS);
            float4 m1 = *(const float4*)(mrow + (size_t)i * TS + 4);
            s[i][0] += m0.x; s[i][1] += m0.y; s[i][2] += m0.z; s[i][3] += m0.w;
            s[i][4] += m1.x; s[i][5] += m1.y; s[i][6] += m1.z; s[i][7] += m1.w;
        }

        // online softmax update (fast-math exp: MUFU.EX2 path)
#pragma unroll
        for (int i = 0; i < 8; i++) {
            float mt = s[i][0];
#pragma unroll
            for (int j = 1; j < 8; j++) mt = fmaxf(mt, s[i][j]);
#pragma unroll
            for (int off = 8; off >= 1; off >>= 1)
                mt = fmaxf(mt, __shfl_xor_sync(0xffffffffu, mt, off));
            float mn = fmaxf(mi[i], mt);
            float al = __expf(mi[i] - mn);
            mi[i] = mn;
            float rs = 0.0f;
#pragma unroll
            for (int j = 0; j < 8; j++) {
                float p = __expf(s[i][j] - mn);
                s[i][j] = p;
                rs += p;
            }
            li[i] = li[i] * al + rs;
            unsigned long long al2 = pack2(al, al);
            fmul2(o2[i][0], al2);
            fmul2(o2[i][1], al2);
            fmul2(o2[i][2], al2);
            fmul2(o2[i][3], al2);
        }

        __syncthreads();   // everyone done reading Ks
        // store P^T into the K buffer: Ps[k][m]
#pragma unroll
        for (int j = 0; j < 8; j++)
#pragma unroll
            for (int i = 0; i < 8; i++)
                Ks[(tx * 8 + j) * 128 + ty * 8 + i] = s[i][j];
        __syncthreads();

        // O += P V  (sum over k)
#pragma unroll 4
        for (int kk = 0; kk < 128; kk++) {
            float4 a0 = *(const float4*)&Ks[kk * 128 + ty * 8];
            float4 a1 = *(const float4*)&Ks[kk * 128 + ty * 8 + 4];
            ulonglong2 b0 = *(const ulonglong2*)&Vs[kk * 128 + tx * 8];
            ulonglong2 b1 = *(const ulonglong2*)&Vs[kk * 128 + tx * 8 + 4];
            float aa[8] = {a0.x, a0.y, a0.z, a0.w, a1.x, a1.y, a1.z, a1.w};
#pragma unroll
            for (int i = 0; i < 8; i++) {
                unsigned long long a2 = pack2(aa[i], aa[i]);
                ffma2(o2[i][0], a2, b0.x);
                ffma2(o2[i][1], a2, b0.y);
                ffma2(o2[i][2], a2, b1.x);
                ffma2(o2[i][3], a2, b1.y);
            }
        }
    }

    // finalize: reduce row sums across tx group, normalize, store to g_AO
#pragma unroll
    for (int i = 0; i < 8; i++) {
        float lt = li[i];
#pragma unroll
        for (int off = 8; off >= 1; off >>= 1)
            lt += __shfl_xor_sync(0xffffffffu, lt, off);
        float inv = 1.0f / lt;
        float o[8];
#pragma unroll
        for (int j4 = 0; j4 < 4; j4++) {
            unpack2(o2[i][j4], o[2 * j4], o[2 * j4 + 1]);
            o[2 * j4] *= inv;
            o[2 * j4 + 1] *= inv;
        }
        float* dst = g_AO + ((size_t)b * TS + (size_t)(mblk * 128 + ty * 8 + i)) * CC
                          + h * DD + tx * 8;
        ((float4*)dst)[0] = make_float4(o[0], o[1], o[2], o[3]);
        ((float4*)dst)[1] = make_float4(o[4], o[5], o[6], o[7]);
    }
}

// ---------------------------------------------------------------------------
// Launch
// ---------------------------------------------------------------------------
extern "C" void kernel_launch(void* const* d_in, const int* in_sizes, int n_in,
                              void* d_out, int out_size)
{
    const float* X   = (const float*)d_in[0];
    const float* msk = (const float*)d_in[1];
    const float* Wq  = (const float*)d_in[2];
    const float* Wk  = (const float*)d_in[3];
    const float* Wv  = (const float*)d_in[4];
    const float* Wo  = (const float*)d_in[5];
    float* out = (float*)d_out;

    cudaFuncSetAttribute(attn_kernel, cudaFuncAttributeMaxDynamicSharedMemorySize,
                         ATT_SMEM);

    // 1) RoPE factor table
    cfac_kernel<<<TS, DD>>>();

    // 2) Q/K/V projections (+rope scale, +1/sqrt(T) folded into Q)
    gemm_kernel<<<dim3(16, 32, 3), 256>>>(X, Wq, Wk, Wv, Wo, nullptr, 0);

    // 3) attention
    attn_kernel<<<dim3(16, 32), 256, ATT_SMEM>>>(msk);

    // 4) output projection -> d_out
    gemm_kernel<<<dim3(16, 32, 1), 256>>>(nullptr, Wq, Wk, Wv, Wo, out, 3);
}

// round 5
// speedup vs baseline: 1.5057x; 1.5057x over previous
#include <cuda_runtime.h>
#include <cuda_bf16.h>
#include <math.h>
#include <stdint.h>

// Problem constants
#define BB 2
#define TS 2048
#define HH 16
#define DD 128
#define CC 2048
#define MMR (BB*TS)
#define KP 6144              // split-K' = 3 * 2048
#define NCHUNK 96            // KP / 64

// 1/sqrt(2048)
#define RSQT 0.022097086912079608f

// ---------------------------------------------------------------------------
// Device scratch
// ---------------------------------------------------------------------------
__device__ float g_Q[(size_t)BB*HH*TS*DD];
__device__ float g_K[(size_t)BB*HH*TS*DD];
__device__ float g_V[(size_t)BB*HH*TS*DD];
__device__ float g_AO[(size_t)MMR*CC];
__device__ float g_cfac[TS*DD];
__device__ __nv_bfloat16 g_Xs [(size_t)MMR*KP];     // [m][k'] : [Xh | Xh | Xl]
__device__ __nv_bfloat16 g_AOs[(size_t)MMR*KP];
__device__ __nv_bfloat16 g_Wt [(size_t)4*CC*KP];    // [w][n][k'] : [Wh | Wl | Wh]

// ---------------------------------------------------------------------------
// PTX helpers (sm_100-baseline-safe: ldmatrix + mma.sync only)
// ---------------------------------------------------------------------------
__device__ __forceinline__ uint32_t smem_u32(const void* p) {
    uint32_t a;
    asm("{ .reg .u64 t; cvta.to.shared.u64 t, %1; cvt.u32.u64 %0, t; }" : "=r"(a) : "l"(p));
    return a;
}
__device__ __forceinline__ void ldsm4(uint32_t* r, uint32_t addr) {
    asm volatile("ldmatrix.sync.aligned.m8n8.x4.shared.b16 {%0,%1,%2,%3}, [%4];"
        : "=r"(r[0]), "=r"(r[1]), "=r"(r[2]), "=r"(r[3]) : "r"(addr));
}
__device__ __forceinline__ void mma16816(float* d, const uint32_t* a, const uint32_t* b) {
    asm volatile("mma.sync.aligned.m16n8k16.row.col.f32.bf16.bf16.f32 "
        "{%0,%1,%2,%3}, {%4,%5,%6,%7}, {%8,%9}, {%0,%1,%2,%3};"
        : "+f"(d[0]), "+f"(d[1]), "+f"(d[2]), "+f"(d[3])
        : "r"(a[0]), "r"(a[1]), "r"(a[2]), "r"(a[3]), "r"(b[0]), "r"(b[1]));
}

// ---------------------------------------------------------------------------
// f32x2 packed helpers (attention kernel)
// ---------------------------------------------------------------------------
__device__ __forceinline__ unsigned long long pack2(float x, float y) {
    unsigned long long r;
    asm("mov.b64 %0, {%1, %2};" : "=l"(r) : "f"(x), "f"(y));
    return r;
}
__device__ __forceinline__ void unpack2(unsigned long long v, float& x, float& y) {
    asm("mov.b64 {%0, %1}, %2;" : "=f"(x), "=f"(y) : "l"(v));
}
__device__ __forceinline__ void ffma2(unsigned long long& c, unsigned long long a,
                                      unsigned long long b) {
    asm("fma.rn.f32x2 %0, %1, %2, %0;" : "+l"(c) : "l"(a), "l"(b));
}
__device__ __forceinline__ void fmul2(unsigned long long& c, unsigned long long a) {
    asm("mul.rn.f32x2 %0, %0, %1;" : "+l"(c) : "l"(a));
}

// ---------------------------------------------------------------------------
// RoPE factor table
// ---------------------------------------------------------------------------
__global__ void cfac_kernel() {
    int t = blockIdx.x;
    int d = threadIdx.x;
    int j = d & 63;
    float ex = (float)(2 * j) / 128.0f;
    float freq = 1.0f / powf(10000.0f, ex);
    float m = (float)t * freq;
    g_cfac[t * DD + d] = cosf(m) + sinf(m);
}

// ---------------------------------------------------------------------------
// Split f32 [4096,2048] into bf16 [4096,6144] = [hi | hi | lo]
// ---------------------------------------------------------------------------
__global__ __launch_bounds__(256) void split_kernel(const float* __restrict__ xin, int useAO) {
    const float* src = useAO ? g_AO : xin;
    __nv_bfloat16* dst = useAO ? g_AOs : g_Xs;
    int idx = blockIdx.x * 256 + threadIdx.x;       // 4096*512
    int m = idx >> 9;
    int kv = (idx & 511) << 2;
    float4 x = *(const float4*)(src + (size_t)m * CC + kv);
    __nv_bfloat16 h0 = __float2bfloat16_rn(x.x);
    __nv_bfloat16 h1 = __float2bfloat16_rn(x.y);
    __nv_bfloat16 h2 = __float2bfloat16_rn(x.z);
    __nv_bfloat16 h3 = __float2bfloat16_rn(x.w);
    __nv_bfloat16 l0 = __float2bfloat16_rn(x.x - __bfloat162float(h0));
    __nv_bfloat16 l1 = __float2bfloat16_rn(x.y - __bfloat162float(h1));
    __nv_bfloat16 l2 = __float2bfloat16_rn(x.z - __bfloat162float(h2));
    __nv_bfloat16 l3 = __float2bfloat16_rn(x.w - __bfloat162float(h3));
    __nv_bfloat162 hA = __halves2bfloat162(h0, h1), hB = __halves2bfloat162(h2, h3);
    __nv_bfloat162 lA = __halves2bfloat162(l0, l1), lB = __halves2bfloat162(l2, l3);
    __nv_bfloat16* p = dst + (size_t)m * KP + kv;
    *(__nv_bfloat162*)(p)          = hA; *(__nv_bfloat162*)(p + 2)        = hB;
    *(__nv_bfloat162*)(p + 2048)   = hA; *(__nv_bfloat162*)(p + 2050)     = hB;
    *(__nv_bfloat162*)(p + 4096)   = lA; *(__nv_bfloat162*)(p + 4098)     = lB;
}

// ---------------------------------------------------------------------------
// Transpose + split weights: Wt[w][n][k'] with [Wh | Wl | Wh]
// ---------------------------------------------------------------------------
__global__ __launch_bounds__(256) void splitW_kernel(
    const float* __restrict__ Wq, const float* __restrict__ Wk,
    const float* __restrict__ Wv, const float* __restrict__ Wo)
{
    __shared__ float tile[32][33];
    int w = blockIdx.z;
    const float* W = (w == 0) ? Wq : (w == 1) ? Wk : (w == 2) ? Wv : Wo;
    __nv_bfloat16* out = g_Wt + (size_t)w * CC * KP;
    int n0 = blockIdx.x * 32, k0 = blockIdx.y * 32;
    int tx = threadIdx.x & 31, ty = threadIdx.x >> 5;   // ty 0..7
#pragma unroll
    for (int r = 0; r < 4; r++) {
        int k = k0 + ty + r * 8;
        tile[ty + r * 8][tx] = W[(size_t)k * CC + n0 + tx];
    }
    __syncthreads();
#pragma unroll
    for (int r = 0; r < 4; r++) {
        int n = n0 + ty + r * 8;
        int k = k0 + tx;
        float x = tile[tx][ty + r * 8];     // = W[k][n]
        __nv_bfloat16 hi = __float2bfloat16_rn(x);
        __nv_bfloat16 lo = __float2bfloat16_rn(x - __bfloat162float(hi));
        __nv_bfloat16* pr = out + (size_t)n * KP;
        pr[k] = hi; pr[2048 + k] = lo; pr[4096 + k] = hi;
    }
}

// ---------------------------------------------------------------------------
// mma.sync bf16 GEMM: 128x128 CTA tile, 8 warps (4m x 2n -> 32x64 warp tile),
// BLK_K=64, double-buffered swizzled smem, K'=6144 in 96 chunks.
// mode 0/1/2: X' @ Wq/k/v' -> g_Q/K/V (rope/scale scatter). mode 3: AO' @ Wo' -> Cout.
// ---------------------------------------------------------------------------
#define SM_TILE 16384                      // 128 rows * 128 bytes
#define SM_TOTAL (4 * SM_TILE)             // A0 B0 A1 B1

__global__ __launch_bounds__(256, 1) void tc_gemm_kernel(int modeBase, float* __restrict__ Cout)
{
    extern __shared__ char smc[];
    uint32_t sb = smem_u32(smc);
    const int tid = threadIdx.x, wid = tid >> 5, lane = tid & 31;
    const int wm = wid >> 1, wn = wid & 1;       // 4 x 2 warp grid
    const int mode = modeBase + (int)blockIdx.z;
    const __nv_bfloat16* A  = (mode == 3) ? g_AOs : g_Xs;
    const __nv_bfloat16* Bp = g_Wt + (size_t)mode * CC * KP;
    const int bm = blockIdx.y, bn = blockIdx.x;

    const __nv_bfloat16* Arow = A  + (size_t)(bm * 128) * KP;
    const __nv_bfloat16* Brow = Bp + (size_t)(bn * 128) * KP;

    // staging indices (each thread: 4 x 16B for A, 4 for B)
    const int ldrow = tid >> 3;          // 0..31, +32 per it
    const int ldc16 = tid & 7;

    float c[2][8][4];
#pragma unroll
    for (int i = 0; i < 2; i++)
#pragma unroll
        for (int j = 0; j < 8; j++)
#pragma unroll
            for (int q = 0; q < 4; q++) c[i][j][q] = 0.0f;

    uint4 stA[4], stB[4];
    // prologue: chunk 0
#pragma unroll
    for (int it = 0; it < 4; it++) {
        int row = ldrow + it * 32;
        stA[it] = *(const uint4*)(Arow + (size_t)row * KP + ldc16 * 8);
        stB[it] = *(const uint4*)(Brow + (size_t)row * KP + ldc16 * 8);
    }
    {
        uint32_t byte = ldrow * 128 + ldc16 * 16;
        uint32_t sw = byte ^ ((ldrow & 7) << 4);
#pragma unroll
        for (int it = 0; it < 4; it++) {
            *(uint4*)(smc + 0 * SM_TILE + sw + it * 4096) = stA[it];
            *(uint4*)(smc + 1 * SM_TILE + sw + it * 4096) = stB[it];
        }
    }
    __syncthreads();

    // per-lane ldmatrix address components
    const int lm16 = lane & 15, lh16 = (lane >> 4) * 16;
    int rowA0 = wm * 32 + lm16;                          // i=0 tile
    int rowB[4];
    const int kbB = ((lane >> 3) & 1) * 16;
    const int rbase = wn * 64 + ((lane >> 4) << 3) + (lane & 7);
#pragma unroll
    for (int g = 0; g < 4; g++) rowB[g] = rbase + g * 16;

    for (int ch = 0; ch < NCHUNK; ch++) {
        int buf = ch & 1;
        // issue next chunk's global loads early
        if (ch + 1 < NCHUNK) {
            int k0 = (ch + 1) * 64;
#pragma unroll
            for (int it = 0; it < 4; it++) {
                int row = ldrow + it * 32;
                stA[it] = *(const uint4*)(Arow + (size_t)row * KP + k0 + ldc16 * 8);
                stB[it] = *(const uint4*)(Brow + (size_t)row * KP + k0 + ldc16 * 8);
            }
        }
        uint32_t sbA = sb + (buf ? 2 * SM_TILE : 0);
        uint32_t sbB = sbA + SM_TILE;
#pragma unroll
        for (int ks = 0; ks < 4; ks++) {
            uint32_t a[2][4], b[4][4];
#pragma unroll
            for (int i = 0; i < 2; i++) {
                int row = rowA0 + i * 16;
                uint32_t kb = ks * 32 + lh16;
                ldsm4(a[i], sbA + row * 128 + (kb ^ ((row & 7) << 4)));
            }
#pragma unroll
            for (int g = 0; g < 4; g++) {
                int row = rowB[g];
                uint32_t kb = ks * 32 + kbB;
                ldsm4(b[g], sbB + row * 128 + (kb ^ ((row & 7) << 4)));
            }
#pragma unroll
            for (int i = 0; i < 2; i++)
#pragma unroll
                for (int j = 0; j < 8; j++)
                    mma16816(c[i][j], a[i], &b[j >> 1][(j & 1) * 2]);
        }
        if (ch + 1 < NCHUNK) {
            uint32_t byte = ldrow * 128 + ldc16 * 16;
            uint32_t sw = byte ^ ((ldrow & 7) << 4);
            char* dstA = smc + (buf ? 0 : 2 * SM_TILE);
#pragma unroll
            for (int it = 0; it < 4; it++) {
                *(uint4*)(dstA + sw + it * 4096) = stA[it];
                *(uint4*)(dstA + SM_TILE + sw + it * 4096) = stB[it];
            }
        }
        __syncthreads();
    }

    // epilogue from mma fragments:
    // d0,d1 -> row = base + lane/4,     cols (lane&3)*2, +1
    // d2,d3 -> row = base + lane/4 + 8, same cols
    const int m0g = bm * 128 + wm * 32;
    const int n0g = bn * 128 + wn * 64;
    const int rsub = lane >> 2, cb = (lane & 3) * 2;
#pragma unroll
    for (int i = 0; i < 2; i++) {
#pragma unroll
        for (int half = 0; half < 2; half++) {
            int row = m0g + i * 16 + rsub + half * 8;
            if (mode == 3) {
                float* drow = Cout + (size_t)row * CC;
#pragma unroll
                for (int j = 0; j < 8; j++) {
                    int col = n0g + j * 8 + cb;
                    *(float2*)(drow + col) = make_float2(c[i][j][half * 2],
                                                         c[i][j][half * 2 + 1]);
                }
            } else {
                int b = row >> 11, t = row & 2047;
                float* outb = (mode == 0) ? g_Q : (mode == 1) ? g_K : g_V;
                float s = (mode == 0) ? RSQT : 1.0f;
#pragma unroll
                for (int j = 0; j < 8; j++) {
                    int col = n0g + j * 8 + cb;
                    int h = col >> 7, d0 = col & 127;
                    float* dst = outb + ((size_t)(b * HH + h) * TS + t) * DD + d0;
                    float v0 = c[i][j][half * 2], v1 = c[i][j][half * 2 + 1];
                    if (mode != 2) {
                        float2 f = *(const float2*)(g_cfac + t * DD + d0);
                        v0 *= f.x * s; v1 *= f.y * s;
                    }
                    *(float2*)dst = make_float2(v0, v1);
                }
            }
        }
    }
}

// ---------------------------------------------------------------------------
// Flash-style attention (unchanged)
// ---------------------------------------------------------------------------
#define ATT_SMEM (3 * 128 * 128 * 4)

__global__ __launch_bounds__(256, 1) void attn_kernel(const float* __restrict__ mask)
{
    extern __shared__ float smem[];
    float* Qs = smem;
    float* Ks = smem + 16384;
    float* Vs = smem + 32768;

    const int tid = threadIdx.x;
    const int tx = tid & 15, ty = tid >> 4;
    const int mblk = blockIdx.x;
    const int bh = blockIdx.y;
    const int b = bh >> 4, h = bh & 15;

    const float* Qg = g_Q + (size_t)bh * TS * DD + (size_t)mblk * 128 * DD;
    const float* Kg = g_K + (size_t)bh * TS * DD;
    const float* Vg = g_V + (size_t)bh * TS * DD;

#pragma unroll
    for (int it = 0; it < 16; it++) {
        int lin = it * 256 + tid;
        int row = lin >> 5;
        int c4 = (lin & 31) << 2;
        float4 v = *(const float4*)(Qg + row * DD + c4);
        Qs[(c4 + 0) * 128 + row] = v.x;
        Qs[(c4 + 1) * 128 + row] = v.y;
        Qs[(c4 + 2) * 128 + row] = v.z;
        Qs[(c4 + 3) * 128 + row] = v.w;
    }

    float mi[8], li[8];
#pragma unroll
    for (int i = 0; i < 8; i++) { mi[i] = __int_as_float(0xff800000u); li[i] = 0.0f; }
    unsigned long long o2[8][4];
#pragma unroll
    for (int i = 0; i < 8; i++)
#pragma unroll
        for (int j = 0; j < 4; j++) o2[i][j] = 0ULL;

    for (int kt = 0; kt < 16; kt++) {
        __syncthreads();
#pragma unroll
        for (int it = 0; it < 16; it++) {
            int lin = it * 256 + tid;
            int row = lin >> 5;
            int c4 = (lin & 31) << 2;
            float4 kv = *(const float4*)(Kg + (size_t)kt * 128 * DD + row * DD + c4);
            Ks[(c4 + 0) * 128 + row] = kv.x;
            Ks[(c4 + 1) * 128 + row] = kv.y;
            Ks[(c4 + 2) * 128 + row] = kv.z;
            Ks[(c4 + 3) * 128 + row] = kv.w;
            float4 vv = *(const float4*)(Vg + (size_t)kt * 128 * DD + row * DD + c4);
            *(float4*)&Vs[row * 128 + c4] = vv;
        }
        __syncthreads();

        unsigned long long s2[8][4];
#pragma unroll
        for (int i = 0; i < 8; i++)
#pragma unroll
            for (int j = 0; j < 4; j++) s2[i][j] = 0ULL;

#pragma unroll 4
        for (int dk = 0; dk < 128; dk++) {
            float4 a0 = *(const float4*)&Qs[dk * 128 + ty * 8];
            float4 a1 = *(const float4*)&Qs[dk * 128 + ty * 8 + 4];
            ulonglong2 b0 = *(const ulonglong2*)&Ks[dk * 128 + tx * 8];
            ulonglong2 b1 = *(const ulonglong2*)&Ks[dk * 128 + tx * 8 + 4];
            float aa[8] = {a0.x, a0.y, a0.z, a0.w, a1.x, a1.y, a1.z, a1.w};
#pragma unroll
            for (int i = 0; i < 8; i++) {
                unsigned long long a2 = pack2(aa[i], aa[i]);
                ffma2(s2[i][0], a2, b0.x);
                ffma2(s2[i][1], a2, b0.y);
                ffma2(s2[i][2], a2, b1.x);
                ffma2(s2[i][3], a2, b1.y);
            }
        }

        float s[8][8];
#pragma unroll
        for (int i = 0; i < 8; i++)
#pragma unroll
            for (int j4 = 0; j4 < 4; j4++)
                unpack2(s2[i][j4], s[i][2 * j4], s[i][2 * j4 + 1]);

        const float* mrow = mask + ((size_t)b * TS + (size_t)(mblk * 128 + ty * 8)) * TS
                                 + (size_t)kt * 128 + tx * 8;
#pragma unroll
        for (int i = 0; i < 8; i++) {
            float4 m0 = *(const float4*)(mrow + (size_t)i * TS);
            float4 m1 = *(const float4*)(mrow + (size_t)i * TS + 4);
            s[i][0] += m0.x; s[i][1] += m0.y; s[i][2] += m0.z; s[i][3] += m0.w;
            s[i][4] += m1.x; s[i][5] += m1.y; s[i][6] += m1.z; s[i][7] += m1.w;
        }

#pragma unroll
        for (int i = 0; i < 8; i++) {
            float mt = s[i][0];
#pragma unroll
            for (int j = 1; j < 8; j++) mt = fmaxf(mt, s[i][j]);
#pragma unroll
            for (int off = 8; off >= 1; off >>= 1)
                mt = fmaxf(mt, __shfl_xor_sync(0xffffffffu, mt, off));
            float mn = fmaxf(mi[i], mt);
            float al = __expf(mi[i] - mn);
            mi[i] = mn;
            float rs = 0.0f;
#pragma unroll
            for (int j = 0; j < 8; j++) {
                float p = __expf(s[i][j] - mn);
                s[i][j] = p;
                rs += p;
            }
            li[i] = li[i] * al + rs;
            unsigned long long al2 = pack2(al, al);
            fmul2(o2[i][0], al2);
            fmul2(o2[i][1], al2);
            fmul2(o2[i][2], al2);
            fmul2(o2[i][3], al2);
        }

        __syncthreads();
#pragma unroll
        for (int j = 0; j < 8; j++)
#pragma unroll
            for (int i = 0; i < 8; i++)
                Ks[(tx * 8 + j) * 128 + ty * 8 + i] = s[i][j];
        __syncthreads();

#pragma unroll 4
        for (int kk = 0; kk < 128; kk++) {
            float4 a0 = *(const float4*)&Ks[kk * 128 + ty * 8];
            float4 a1 = *(const float4*)&Ks[kk * 128 + ty * 8 + 4];
            ulonglong2 b0 = *(const ulonglong2*)&Vs[kk * 128 + tx * 8];
            ulonglong2 b1 = *(const ulonglong2*)&Vs[kk * 128 + tx * 8 + 4];
            float aa[8] = {a0.x, a0.y, a0.z, a0.w, a1.x, a1.y, a1.z, a1.w};
#pragma unroll
            for (int i = 0; i < 8; i++) {
                unsigned long long a2 = pack2(aa[i], aa[i]);
                ffma2(o2[i][0], a2, b0.x);
                ffma2(o2[i][1], a2, b0.y);
                ffma2(o2[i][2], a2, b1.x);
                ffma2(o2[i][3], a2, b1.y);
            }
        }
    }

#pragma unroll
    for (int i = 0; i < 8; i++) {
        float lt = li[i];
#pragma unroll
        for (int off = 8; off >= 1; off >>= 1)
            lt += __shfl_xor_sync(0xffffffffu, lt, off);
        float inv = 1.0f / lt;
        float o[8];
#pragma unroll
        for (int j4 = 0; j4 < 4; j4++) {
            unpack2(o2[i][j4], o[2 * j4], o[2 * j4 + 1]);
            o[2 * j4] *= inv;
            o[2 * j4 + 1] *= inv;
        }
        float* dst = g_AO + ((size_t)b * TS + (size_t)(mblk * 128 + ty * 8 + i)) * CC
                          + h * DD + tx * 8;
        ((float4*)dst)[0] = make_float4(o[0], o[1], o[2], o[3]);
        ((float4*)dst)[1] = make_float4(o[4], o[5], o[6], o[7]);
    }
}

// ---------------------------------------------------------------------------
// Launch
// ---------------------------------------------------------------------------
extern "C" void kernel_launch(void* const* d_in, const int* in_sizes, int n_in,
                              void* d_out, int out_size)
{
    const float* X   = (const float*)d_in[0];
    const float* msk = (const float*)d_in[1];
    const float* Wq  = (const float*)d_in[2];
    const float* Wk  = (const float*)d_in[3];
    const float* Wv  = (const float*)d_in[4];
    const float* Wo  = (const float*)d_in[5];
    float* out = (float*)d_out;

    cudaFuncSetAttribute(attn_kernel, cudaFuncAttributeMaxDynamicSharedMemorySize, ATT_SMEM);
    cudaFuncSetAttribute(tc_gemm_kernel, cudaFuncAttributeMaxDynamicSharedMemorySize, SM_TOTAL);

    cfac_kernel<<<TS, DD>>>();
    splitW_kernel<<<dim3(64, 64, 4), 256>>>(Wq, Wk, Wv, Wo);
    split_kernel<<<8192, 256>>>(X, 0);

    // QKV projections on tensor cores (mma.sync)
    tc_gemm_kernel<<<dim3(16, 32, 3), 256, SM_TOTAL>>>(0, nullptr);

    attn_kernel<<<dim3(16, 32), 256, ATT_SMEM>>>(msk);

    split_kernel<<<8192, 256>>>(nullptr, 1);
    tc_gemm_kernel<<<dim3(16, 32, 1), 256, SM_TOTAL>>>(3, out);
}

// round 6
// speedup vs baseline: 3.2477x; 2.1569x over previous
#include <cuda_runtime.h>
#include <cuda_bf16.h>
#include <math.h>
#include <stdint.h>

// Problem constants
#define BB 2
#define TS 2048
#define HH 16
#define DD 128
#define CC 2048
#define MMR (BB*TS)
#define KP 6144              // split-K' = 3 * 2048
#define NCHUNK 96            // KP / 64

// 1/sqrt(2048)
#define RSQT 0.022097086912079608f

// ---------------------------------------------------------------------------
// Device scratch
// ---------------------------------------------------------------------------
__device__ float g_V [(size_t)BB*HH*TS*DD];          // fp32 V [bh][t][d]
__device__ float g_AO[(size_t)MMR*CC];
__device__ float g_cfac[TS*DD];
__device__ __nv_bfloat16 g_Qh[(size_t)BB*HH*TS*DD];  // [bh][t][d]
__device__ __nv_bfloat16 g_Ql[(size_t)BB*HH*TS*DD];
__device__ __nv_bfloat16 g_Kh[(size_t)BB*HH*TS*DD];
__device__ __nv_bfloat16 g_Kl[(size_t)BB*HH*TS*DD];
__device__ __nv_bfloat16 g_Vth[(size_t)BB*HH*TS*DD]; // V^T hi [bh][d][t]
__device__ __nv_bfloat16 g_Vtl[(size_t)BB*HH*TS*DD]; // V^T lo
__device__ __nv_bfloat16 g_Xs [(size_t)MMR*KP];      // [m][k'] : [Xh | Xh | Xl]
__device__ __nv_bfloat16 g_AOs[(size_t)MMR*KP];
__device__ __nv_bfloat16 g_Wt [(size_t)4*CC*KP];     // [w][n][k'] : [Wh | Wl | Wh]

// ---------------------------------------------------------------------------
// PTX helpers (sm_100-baseline-safe)
// ---------------------------------------------------------------------------
__device__ __forceinline__ uint32_t smem_u32(const void* p) {
    uint32_t a;
    asm("{ .reg .u64 t; cvta.to.shared.u64 t, %1; cvt.u32.u64 %0, t; }" : "=r"(a) : "l"(p));
    return a;
}
__device__ __forceinline__ void ldsm4(uint32_t* r, uint32_t addr) {
    asm volatile("ldmatrix.sync.aligned.m8n8.x4.shared.b16 {%0,%1,%2,%3}, [%4];"
        : "=r"(r[0]), "=r"(r[1]), "=r"(r[2]), "=r"(r[3]) : "r"(addr));
}
__device__ __forceinline__ void mma16816(float* d, const uint32_t* a, const uint32_t* b) {
    asm volatile("mma.sync.aligned.m16n8k16.row.col.f32.bf16.bf16.f32 "
        "{%0,%1,%2,%3}, {%4,%5,%6,%7}, {%8,%9}, {%0,%1,%2,%3};"
        : "+f"(d[0]), "+f"(d[1]), "+f"(d[2]), "+f"(d[3])
        : "r"(a[0]), "r"(a[1]), "r"(a[2]), "r"(a[3]), "r"(b[0]), "r"(b[1]));
}
__device__ __forceinline__ void cpa16(uint32_t s, const void* g) {
    asm volatile("cp.async.cg.shared.global [%0], [%1], 16;" :: "r"(s), "l"(g));
}
#define CP_COMMIT() asm volatile("cp.async.commit_group;")
#define CP_WAIT(n)  asm volatile("cp.async.wait_group %0;" :: "n"(n))

__device__ __forceinline__ uint32_t bf2u(__nv_bfloat16 a, __nv_bfloat16 b) {
    __nv_bfloat162 t = __halves2bfloat162(a, b);
    return *(uint32_t*)&t;
}
// swizzled smem address for 256B-row tiles
#define ASW(base, r, kb) ((base) + (uint32_t)(r) * 256 + (((uint32_t)(kb)) ^ ((((uint32_t)(r)) & 7) << 4)))

// ---------------------------------------------------------------------------
// RoPE factor table
// ---------------------------------------------------------------------------
__global__ void cfac_kernel() {
    int t = blockIdx.x;
    int d = threadIdx.x;
    int j = d & 63;
    float ex = (float)(2 * j) / 128.0f;
    float freq = 1.0f / powf(10000.0f, ex);
    float m = (float)t * freq;
    g_cfac[t * DD + d] = cosf(m) + sinf(m);
}

// ---------------------------------------------------------------------------
// Split f32 [4096,2048] into bf16 [4096,6144] = [hi | hi | lo]
// ---------------------------------------------------------------------------
__global__ __launch_bounds__(256) void split_kernel(const float* __restrict__ xin, int useAO) {
    const float* src = useAO ? g_AO : xin;
    __nv_bfloat16* dst = useAO ? g_AOs : g_Xs;
    int idx = blockIdx.x * 256 + threadIdx.x;
    int m = idx >> 9;
    int kv = (idx & 511) << 2;
    float4 x = *(const float4*)(src + (size_t)m * CC + kv);
    __nv_bfloat16 h0 = __float2bfloat16_rn(x.x);
    __nv_bfloat16 h1 = __float2bfloat16_rn(x.y);
    __nv_bfloat16 h2 = __float2bfloat16_rn(x.z);
    __nv_bfloat16 h3 = __float2bfloat16_rn(x.w);
    __nv_bfloat16 l0 = __float2bfloat16_rn(x.x - __bfloat162float(h0));
    __nv_bfloat16 l1 = __float2bfloat16_rn(x.y - __bfloat162float(h1));
    __nv_bfloat16 l2 = __float2bfloat16_rn(x.z - __bfloat162float(h2));
    __nv_bfloat16 l3 = __float2bfloat16_rn(x.w - __bfloat162float(h3));
    __nv_bfloat162 hA = __halves2bfloat162(h0, h1), hB = __halves2bfloat162(h2, h3);
    __nv_bfloat162 lA = __halves2bfloat162(l0, l1), lB = __halves2bfloat162(l2, l3);
    __nv_bfloat16* p = dst + (size_t)m * KP + kv;
    *(__nv_bfloat162*)(p)        = hA; *(__nv_bfloat162*)(p + 2)    = hB;
    *(__nv_bfloat162*)(p + 2048) = hA; *(__nv_bfloat162*)(p + 2050) = hB;
    *(__nv_bfloat162*)(p + 4096) = lA; *(__nv_bfloat162*)(p + 4098) = lB;
}

// ---------------------------------------------------------------------------
// Transpose + split weights: Wt[w][n][k'] with [Wh | Wl | Wh]
// ---------------------------------------------------------------------------
__global__ __launch_bounds__(256) void splitW_kernel(
    const float* __restrict__ Wq, const float* __restrict__ Wk,
    const float* __restrict__ Wv, const float* __restrict__ Wo)
{
    __shared__ float tile[32][33];
    int w = blockIdx.z;
    const float* W = (w == 0) ? Wq : (w == 1) ? Wk : (w == 2) ? Wv : Wo;
    __nv_bfloat16* out = g_Wt + (size_t)w * CC * KP;
    int n0 = blockIdx.x * 32, k0 = blockIdx.y * 32;
    int tx = threadIdx.x & 31, ty = threadIdx.x >> 5;
#pragma unroll
    for (int r = 0; r < 4; r++) {
        int k = k0 + ty + r * 8;
        tile[ty + r * 8][tx] = W[(size_t)k * CC + n0 + tx];
    }
    __syncthreads();
#pragma unroll
    for (int r = 0; r < 4; r++) {
        int n = n0 + ty + r * 8;
        int k = k0 + tx;
        float x = tile[tx][ty + r * 8];
        __nv_bfloat16 hi = __float2bfloat16_rn(x);
        __nv_bfloat16 lo = __float2bfloat16_rn(x - __bfloat162float(hi));
        __nv_bfloat16* pr = out + (size_t)n * KP;
        pr[k] = hi; pr[2048 + k] = lo; pr[4096 + k] = hi;
    }
}

// ---------------------------------------------------------------------------
// V transpose+split: g_V fp32 [bh][t][d] -> g_Vth/g_Vtl bf16 [bh][d][t]
// ---------------------------------------------------------------------------
__global__ __launch_bounds__(256) void vtrans_kernel() {
    __shared__ float tile[32][33];
    int bh = blockIdx.z, t0 = blockIdx.x * 32, d0 = blockIdx.y * 32;
    int tx = threadIdx.x & 31, ty = threadIdx.x >> 5;
    const float* src = g_V + (size_t)bh * TS * DD;
#pragma unroll
    for (int r = 0; r < 4; r++)
        tile[ty + r * 8][tx] = src[(size_t)(t0 + ty + r * 8) * DD + d0 + tx];
    __syncthreads();
#pragma unroll
    for (int r = 0; r < 4; r++) {
        int d = d0 + ty + r * 8;
        int t = t0 + tx;
        float v = tile[tx][ty + r * 8];
        __nv_bfloat16 hv = __float2bfloat16_rn(v);
        __nv_bfloat16 lv = __float2bfloat16_rn(v - __bfloat162float(hv));
        size_t off = (size_t)bh * DD * TS + (size_t)d * TS + t;
        g_Vth[off] = hv;
        g_Vtl[off] = lv;
    }
}

// ---------------------------------------------------------------------------
// mma.sync bf16 GEMM with cp.async staging, 2 CTAs/SM.
// mode 0: -> g_Qh/g_Ql (rope*RSQT) ; mode 1: -> g_Kh/g_Kl (rope)
// mode 2: -> g_V fp32 ; mode 3: AO' @ Wo' -> Cout
// ---------------------------------------------------------------------------
#define SM_TILE 16384
#define SM_TOTAL (4 * SM_TILE)

__global__ __launch_bounds__(256, 2) void tc_gemm_kernel(int modeBase, float* __restrict__ Cout)
{
    extern __shared__ char smc[];
    uint32_t sb = smem_u32(smc);
    const int tid = threadIdx.x, wid = tid >> 5, lane = tid & 31;
    const int wm = wid >> 1, wn = wid & 1;
    const int mode = modeBase + (int)blockIdx.z;
    const __nv_bfloat16* A  = (mode == 3) ? g_AOs : g_Xs;
    const __nv_bfloat16* Bp = g_Wt + (size_t)mode * CC * KP;
    const int bm = blockIdx.y, bn = blockIdx.x;

    const __nv_bfloat16* Arow = A  + (size_t)(bm * 128) * KP;
    const __nv_bfloat16* Brow = Bp + (size_t)(bn * 128) * KP;

    const int ldrow = tid >> 3;
    const int ldc16 = tid & 7;
    const uint32_t sw = ((uint32_t)(ldrow * 128 + ldc16 * 16)) ^ ((ldrow & 7) << 4);

    float c[2][8][4];
#pragma unroll
    for (int i = 0; i < 2; i++)
#pragma unroll
        for (int j = 0; j < 8; j++)
#pragma unroll
            for (int q = 0; q < 4; q++) c[i][j][q] = 0.0f;

    // prologue: chunk 0 -> buf 0
#pragma unroll
    for (int it = 0; it < 4; it++) {
        int row = ldrow + it * 32;
        cpa16(sb + sw + it * 4096,            Arow + (size_t)row * KP + ldc16 * 8);
        cpa16(sb + SM_TILE + sw + it * 4096,  Brow + (size_t)row * KP + ldc16 * 8);
    }
    CP_COMMIT();

    const int lm16 = lane & 15, lh16 = (lane >> 4) * 16;
    const int rowA0 = wm * 32 + lm16;
    const int kbB = ((lane >> 3) & 1) * 16;
    const int rbase = wn * 64 + ((lane >> 4) << 3) + (lane & 7);

    for (int ch = 0; ch < NCHUNK; ch++) {
        int buf = ch & 1;
        if (ch + 1 < NCHUNK) {
            int k0 = (ch + 1) * 64;
            uint32_t db = sb + ((ch + 1) & 1) * 2 * SM_TILE;
#pragma unroll
            for (int it = 0; it < 4; it++) {
                int row = ldrow + it * 32;
                cpa16(db + sw + it * 4096,           Arow + (size_t)row * KP + k0 + ldc16 * 8);
                cpa16(db + SM_TILE + sw + it * 4096, Brow + (size_t)row * KP + k0 + ldc16 * 8);
            }
            CP_COMMIT();
            CP_WAIT(1);
        } else {
            CP_WAIT(0);
        }
        __syncthreads();

        uint32_t sbA = sb + (buf ? 2 * SM_TILE : 0);
        uint32_t sbB = sbA + SM_TILE;
#pragma unroll
        for (int ks = 0; ks < 4; ks++) {
            uint32_t a[2][4], b[4][4];
#pragma unroll
            for (int i = 0; i < 2; i++) {
                int row = rowA0 + i * 16;
                uint32_t kb = ks * 32 + lh16;
                ldsm4(a[i], sbA + row * 128 + (kb ^ ((row & 7) << 4)));
            }
#pragma unroll
            for (int g = 0; g < 4; g++) {
                int row = rbase + g * 16;
                uint32_t kb = ks * 32 + kbB;
                ldsm4(b[g], sbB + row * 128 + (kb ^ ((row & 7) << 4)));
            }
#pragma unroll
            for (int i = 0; i < 2; i++)
#pragma unroll
                for (int j = 0; j < 8; j++)
                    mma16816(c[i][j], a[i], &b[j >> 1][(j & 1) * 2]);
        }
        __syncthreads();
    }

    // epilogue
    const int m0g = bm * 128 + wm * 32;
    const int n0g = bn * 128 + wn * 64;
    const int rsub = lane >> 2, cb = (lane & 3) * 2;
#pragma unroll
    for (int i = 0; i < 2; i++) {
#pragma unroll
        for (int half = 0; half < 2; half++) {
            int row = m0g + i * 16 + rsub + half * 8;
            if (mode == 3) {
                float* drow = Cout + (size_t)row * CC;
#pragma unroll
                for (int j = 0; j < 8; j++) {
                    int col = n0g + j * 8 + cb;
                    *(float2*)(drow + col) = make_float2(c[i][j][half * 2],
                                                         c[i][j][half * 2 + 1]);
                }
            } else if (mode == 2) {
                int b = row >> 11, t = row & 2047;
#pragma unroll
                for (int j = 0; j < 8; j++) {
                    int col = n0g + j * 8 + cb;
                    int h = col >> 7, d0 = col & 127;
                    float* dst = g_V + ((size_t)(b * HH + h) * TS + t) * DD + d0;
                    *(float2*)dst = make_float2(c[i][j][half * 2], c[i][j][half * 2 + 1]);
                }
            } else {
                int b = row >> 11, t = row & 2047;
                __nv_bfloat16* outH = (mode == 0) ? g_Qh : g_Kh;
                __nv_bfloat16* outL = (mode == 0) ? g_Ql : g_Kl;
                float s = (mode == 0) ? RSQT : 1.0f;
#pragma unroll
                for (int j = 0; j < 8; j++) {
                    int col = n0g + j * 8 + cb;
                    int h = col >> 7, d0 = col & 127;
                    float2 f = *(const float2*)(g_cfac + t * DD + d0);
                    float v0 = c[i][j][half * 2]     * f.x * s;
                    float v1 = c[i][j][half * 2 + 1] * f.y * s;
                    __nv_bfloat16 h0 = __float2bfloat16_rn(v0);
                    __nv_bfloat16 h1 = __float2bfloat16_rn(v1);
                    __nv_bfloat16 l0 = __float2bfloat16_rn(v0 - __bfloat162float(h0));
                    __nv_bfloat16 l1 = __float2bfloat16_rn(v1 - __bfloat162float(h1));
                    size_t off = ((size_t)(b * HH + h) * TS + t) * DD + d0;
                    *(uint32_t*)(outH + off) = bf2u(h0, h1);
                    *(uint32_t*)(outL + off) = bf2u(l0, l1);
                }
            }
        }
    }
}

// ---------------------------------------------------------------------------
// Tensor-core flash attention, split-bf16 (3-term) for S and PV.
// One CTA per (128 q-rows, b*h); 8 warps, each owns 16 q-rows x 128 cols.
// smem: QH QL (resident) | KH KL | VH VL  (each 32KB, 192KB total)
// ---------------------------------------------------------------------------
#define ATT_SMEM 196608

__global__ __launch_bounds__(256, 1) void attn_kernel(const float* __restrict__ mask)
{
    extern __shared__ char smc[];
    uint32_t sb = smem_u32(smc);
    const int tid = threadIdx.x, wid = tid >> 5, lane = tid & 31;
    const int mblk = blockIdx.x, bh = blockIdx.y;
    const int b = bh >> 4, h = bh & 15;

    const uint32_t QH = sb, QL = sb + 32768, KH = sb + 65536, KL = sb + 98304,
                   VH = sb + 131072, VL = sb + 163840;

    const size_t qoff = (size_t)bh * TS * DD + (size_t)mblk * 128 * DD;   // elements
    const size_t koff = (size_t)bh * TS * DD;
    const size_t voff = (size_t)bh * DD * TS;

    // Q hi/lo resident load (group 0)
#pragma unroll
    for (int it = 0; it < 8; it++) {
        int id = it * 256 + tid;
        int r = id >> 4;
        uint32_t kb = (id & 15) * 16;
        const char* gq = (const char*)g_Qh + ((qoff + (size_t)r * DD) << 1) + kb;
        const char* gl = (const char*)g_Ql + ((qoff + (size_t)r * DD) << 1) + kb;
        cpa16(ASW(QH, r, kb), gq);
        cpa16(ASW(QL, r, kb), gl);
    }
    CP_COMMIT();

    const int rsub = lane >> 2, cb = (lane & 3) * 2;
    const int q0 = mblk * 128 + wid * 16 + rsub;        // local q row (within bh)
    const int kbB = ((lane >> 3) & 1) * 16;
    const int rbB = (lane & 7) + ((lane >> 4) << 3);
    const int raA = wid * 16 + (lane & 15);
    const uint32_t kbA = (lane >> 4) * 16;

    float mr0 = -1e30f, mr1 = -1e30f, lr0 = 0.0f, lr1 = 0.0f;
    float o[16][4];
#pragma unroll
    for (int j = 0; j < 16; j++)
#pragma unroll
        for (int q = 0; q < 4; q++) o[j][q] = 0.0f;

    for (int kt = 0; kt < 16; kt++) {
        __syncthreads();   // all warps done with previous tile's K/V
        // K tile (group)
#pragma unroll
        for (int it = 0; it < 8; it++) {
            int id = it * 256 + tid;
            int r = id >> 4;
            uint32_t kb = (id & 15) * 16;
            size_t ge = koff + (size_t)(kt * 128 + r) * DD;
            cpa16(ASW(KH, r, kb), (const char*)g_Kh + (ge << 1) + kb);
            cpa16(ASW(KL, r, kb), (const char*)g_Kl + (ge << 1) + kb);
        }
        CP_COMMIT();
        // V tile (group) — rows d, cols keys
#pragma unroll
        for (int it = 0; it < 8; it++) {
            int id = it * 256 + tid;
            int r = id >> 4;
            uint32_t kb = (id & 15) * 16;
            size_t ge = voff + (size_t)r * TS + kt * 128;
            cpa16(ASW(VH, r, kb), (const char*)g_Vth + (ge << 1) + kb);
            cpa16(ASW(VL, r, kb), (const char*)g_Vtl + (ge << 1) + kb);
        }
        CP_COMMIT();
        CP_WAIT(1);        // Q + K ready (V may be in flight)
        __syncthreads();

        // ---- S = Qh*Kh + Qh*Kl + Ql*Kh ----
        float s[16][4];
#pragma unroll
        for (int j = 0; j < 16; j++)
#pragma unroll
            for (int q = 0; q < 4; q++) s[j][q] = 0.0f;

#pragma unroll
        for (int ks = 0; ks < 8; ks++) {
            uint32_t aH[4], aL[4], bHf[8][4], bLf[8][4];
            uint32_t kba = ks * 32 + kbA;
            ldsm4(aH, ASW(QH, raA, kba));
            ldsm4(aL, ASW(QL, raA, kba));
#pragma unroll
            for (int g = 0; g < 8; g++) {
                int rb = g * 16 + rbB;
                uint32_t kb = ks * 32 + kbB;
                ldsm4(bHf[g], ASW(KH, rb, kb));
                ldsm4(bLf[g], ASW(KL, rb, kb));
            }
#pragma unroll
            for (int j = 0; j < 16; j++) {
                mma16816(s[j], aH, &bHf[j >> 1][(j & 1) * 2]);
                mma16816(s[j], aH, &bLf[j >> 1][(j & 1) * 2]);
                mma16816(s[j], aL, &bHf[j >> 1][(j & 1) * 2]);
            }
        }

        // ---- mask add ----
        const float* mrow0 = mask + ((size_t)b * TS + q0) * TS + (size_t)kt * 128;
        const float* mrow1 = mrow0 + (size_t)8 * TS;
#pragma unroll
        for (int j = 0; j < 16; j++) {
            float2 m0 = *(const float2*)(mrow0 + j * 8 + cb);
            float2 m1 = *(const float2*)(mrow1 + j * 8 + cb);
            s[j][0] += m0.x; s[j][1] += m0.y;
            s[j][2] += m1.x; s[j][3] += m1.y;
        }

        // ---- online softmax (rows q0, q0+8) ----
        float mt0 = -1e30f, mt1 = -1e30f;
#pragma unroll
        for (int j = 0; j < 16; j++) {
            mt0 = fmaxf(mt0, fmaxf(s[j][0], s[j][1]));
            mt1 = fmaxf(mt1, fmaxf(s[j][2], s[j][3]));
        }
        mt0 = fmaxf(mt0, __shfl_xor_sync(0xffffffffu, mt0, 1));
        mt0 = fmaxf(mt0, __shfl_xor_sync(0xffffffffu, mt0, 2));
        mt1 = fmaxf(mt1, __shfl_xor_sync(0xffffffffu, mt1, 1));
        mt1 = fmaxf(mt1, __shfl_xor_sync(0xffffffffu, mt1, 2));
        float mn0 = fmaxf(mr0, mt0), mn1 = fmaxf(mr1, mt1);
        float al0 = __expf(mr0 - mn0), al1 = __expf(mr1 - mn1);
        mr0 = mn0; mr1 = mn1;
        float rs0 = 0.0f, rs1 = 0.0f;
#pragma unroll
        for (int j = 0; j < 16; j++) {
            s[j][0] = __expf(s[j][0] - mn0); rs0 += s[j][0];
            s[j][1] = __expf(s[j][1] - mn0); rs0 += s[j][1];
            s[j][2] = __expf(s[j][2] - mn1); rs1 += s[j][2];
            s[j][3] = __expf(s[j][3] - mn1); rs1 += s[j][3];
        }
        rs0 += __shfl_xor_sync(0xffffffffu, rs0, 1);
        rs0 += __shfl_xor_sync(0xffffffffu, rs0, 2);
        rs1 += __shfl_xor_sync(0xffffffffu, rs1, 1);
        rs1 += __shfl_xor_sync(0xffffffffu, rs1, 2);
        lr0 = lr0 * al0 + rs0;
        lr1 = lr1 * al1 + rs1;
#pragma unroll
        for (int j = 0; j < 16; j++) {
            o[j][0] *= al0; o[j][1] *= al0;
            o[j][2] *= al1; o[j][3] *= al1;
        }

        CP_WAIT(0);        // V ready
        __syncthreads();

        // ---- O += Ph*Vh + Ph*Vl + Pl*Vh ----
#pragma unroll
        for (int ks = 0; ks < 8; ks++) {
            // P fragments directly from s (C-frag layout == A-frag layout)
            uint32_t ah[4], alr[4];
#pragma unroll
            for (int half = 0; half < 2; half++) {
                int j = 2 * ks + half;
                __nv_bfloat16 h0 = __float2bfloat16_rn(s[j][0]);
                __nv_bfloat16 h1 = __float2bfloat16_rn(s[j][1]);
                __nv_bfloat16 h2 = __float2bfloat16_rn(s[j][2]);
                __nv_bfloat16 h3 = __float2bfloat16_rn(s[j][3]);
                ah[half * 2 + 0] = bf2u(h0, h1);
                ah[half * 2 + 1] = bf2u(h2, h3);
                __nv_bfloat16 l0 = __float2bfloat16_rn(s[j][0] - __bfloat162float(h0));
                __nv_bfloat16 l1 = __float2bfloat16_rn(s[j][1] - __bfloat162float(h1));
                __nv_bfloat16 l2 = __float2bfloat16_rn(s[j][2] - __bfloat162float(h2));
                __nv_bfloat16 l3 = __float2bfloat16_rn(s[j][3] - __bfloat162float(h3));
                alr[half * 2 + 0] = bf2u(l0, l1);
                alr[half * 2 + 1] = bf2u(l2, l3);
            }
            uint32_t bHf[8][4], bLf[8][4];
#pragma unroll
            for (int g = 0; g < 8; g++) {
                int rb = g * 16 + rbB;
                uint32_t kb = ks * 32 + kbB;
                ldsm4(bHf[g], ASW(VH, rb, kb));
                ldsm4(bLf[g], ASW(VL, rb, kb));
            }
#pragma unroll
            for (int j = 0; j < 16; j++) {
                mma16816(o[j], ah, &bHf[j >> 1][(j & 1) * 2]);
                mma16816(o[j], ah, &bLf[j >> 1][(j & 1) * 2]);
                mma16816(o[j], alr, &bHf[j >> 1][(j & 1) * 2]);
            }
        }
    }

    // ---- finalize ----
    float inv0 = 1.0f / lr0, inv1 = 1.0f / lr1;
    float* d0row = g_AO + ((size_t)b * TS + q0) * CC + h * DD;
    float* d1row = d0row + (size_t)8 * CC;
#pragma unroll
    for (int j = 0; j < 16; j++) {
        *(float2*)(d0row + j * 8 + cb) = make_float2(o[j][0] * inv0, o[j][1] * inv0);
        *(float2*)(d1row + j * 8 + cb) = make_float2(o[j][2] * inv1, o[j][3] * inv1);
    }
}

// ---------------------------------------------------------------------------
// Launch
// ---------------------------------------------------------------------------
extern "C" void kernel_launch(void* const* d_in, const int* in_sizes, int n_in,
                              void* d_out, int out_size)
{
    const float* X   = (const float*)d_in[0];
    const float* msk = (const float*)d_in[1];
    const float* Wq  = (const float*)d_in[2];
    const float* Wk  = (const float*)d_in[3];
    const float* Wv  = (const float*)d_in[4];
    const float* Wo  = (const float*)d_in[5];
    float* out = (float*)d_out;

    cudaFuncSetAttribute(attn_kernel, cudaFuncAttributeMaxDynamicSharedMemorySize, ATT_SMEM);
    cudaFuncSetAttribute(tc_gemm_kernel, cudaFuncAttributeMaxDynamicSharedMemorySize, SM_TOTAL);

    cfac_kernel<<<TS, DD>>>();
    splitW_kernel<<<dim3(64, 64, 4), 256>>>(Wq, Wk, Wv, Wo);
    split_kernel<<<8192, 256>>>(X, 0);

    // QKV projections (mma.sync, bf16-split epilogues)
    tc_gemm_kernel<<<dim3(16, 32, 3), 256, SM_TOTAL>>>(0, nullptr);

    vtrans_kernel<<<dim3(64, 4, 32), 256>>>();

    attn_kernel<<<dim3(16, 32), 256, ATT_SMEM>>>(msk);

    split_kernel<<<8192, 256>>>(nullptr, 1);
    tc_gemm_kernel<<<dim3(16, 32, 1), 256, SM_TOTAL>>>(3, out);
}

// round 7
// speedup vs baseline: 3.2498x; 1.0007x over previous
#include <cuda_runtime.h>
#include <cuda_bf16.h>
#include <math.h>
#include <stdint.h>

// Problem constants
#define BB 2
#define TS 2048
#define HH 16
#define DD 128
#define CC 2048
#define MMR (BB*TS)
#define KPA 4096             // compact split stride: [hi | lo]
#define NCHUNK 96            // logical K' = 3*2048 in 96 chunks of 64

// 1/sqrt(2048)
#define RSQT 0.022097086912079608f

// ---------------------------------------------------------------------------
// Device scratch
// ---------------------------------------------------------------------------
__device__ float g_V [(size_t)BB*HH*TS*DD];          // fp32 V [bh][t][d]
__device__ float g_cfac[TS*DD];
__device__ __nv_bfloat16 g_Qh[(size_t)BB*HH*TS*DD];  // [bh][t][d]
__device__ __nv_bfloat16 g_Ql[(size_t)BB*HH*TS*DD];
__device__ __nv_bfloat16 g_Kh[(size_t)BB*HH*TS*DD];
__device__ __nv_bfloat16 g_Kl[(size_t)BB*HH*TS*DD];
__device__ __nv_bfloat16 g_Vth[(size_t)BB*HH*TS*DD]; // V^T hi [bh][d][t]
__device__ __nv_bfloat16 g_Vtl[(size_t)BB*HH*TS*DD]; // V^T lo
__device__ __nv_bfloat16 g_Xs [(size_t)MMR*KPA];     // [m][4096] : [Xh | Xl]
__device__ __nv_bfloat16 g_AOs[(size_t)MMR*KPA];     // [m][4096] : [AOh | AOl]
__device__ __nv_bfloat16 g_Wt [(size_t)4*CC*KPA];    // [w][n][4096] : [Wh | Wl]

// ---------------------------------------------------------------------------
// PTX helpers (sm_100-baseline-safe)
// ---------------------------------------------------------------------------
__device__ __forceinline__ uint32_t smem_u32(const void* p) {
    uint32_t a;
    asm("{ .reg .u64 t; cvta.to.shared.u64 t, %1; cvt.u32.u64 %0, t; }" : "=r"(a) : "l"(p));
    return a;
}
__device__ __forceinline__ void ldsm4(uint32_t* r, uint32_t addr) {
    asm volatile("ldmatrix.sync.aligned.m8n8.x4.shared.b16 {%0,%1,%2,%3}, [%4];"
        : "=r"(r[0]), "=r"(r[1]), "=r"(r[2]), "=r"(r[3]) : "r"(addr));
}
__device__ __forceinline__ void mma16816(float* d, const uint32_t* a, const uint32_t* b) {
    asm volatile("mma.sync.aligned.m16n8k16.row.col.f32.bf16.bf16.f32 "
        "{%0,%1,%2,%3}, {%4,%5,%6,%7}, {%8,%9}, {%0,%1,%2,%3};"
        : "+f"(d[0]), "+f"(d[1]), "+f"(d[2]), "+f"(d[3])
        : "r"(a[0]), "r"(a[1]), "r"(a[2]), "r"(a[3]), "r"(b[0]), "r"(b[1]));
}
__device__ __forceinline__ void cpa16(uint32_t s, const void* g) {
    asm volatile("cp.async.cg.shared.global [%0], [%1], 16;" :: "r"(s), "l"(g));
}
#define CP_COMMIT() asm volatile("cp.async.commit_group;")
#define CP_WAIT(n)  asm volatile("cp.async.wait_group %0;" :: "n"(n))

__device__ __forceinline__ uint32_t bf2u(__nv_bfloat16 a, __nv_bfloat16 b) {
    __nv_bfloat162 t = __halves2bfloat162(a, b);
    return *(uint32_t*)&t;
}
// swizzled smem address for 256B-row tiles (attention)
#define ASW(base, r, kb) ((base) + (uint32_t)(r) * 256 + (((uint32_t)(kb)) ^ ((((uint32_t)(r)) & 7) << 4)))

// ---------------------------------------------------------------------------
// RoPE factor table
// ---------------------------------------------------------------------------
__global__ void cfac_kernel() {
    int t = blockIdx.x;
    int d = threadIdx.x;
    int j = d & 63;
    float ex = (float)(2 * j) / 128.0f;
    float freq = 1.0f / powf(10000.0f, ex);
    float m = (float)t * freq;
    g_cfac[t * DD + d] = cosf(m) + sinf(m);
}

// ---------------------------------------------------------------------------
// Split f32 [4096,2048] into compact bf16 [4096,4096] = [hi | lo]
// ---------------------------------------------------------------------------
__global__ __launch_bounds__(256) void split_kernel(const float* __restrict__ xin) {
    int idx = blockIdx.x * 256 + threadIdx.x;
    int m = idx >> 9;
    int kv = (idx & 511) << 2;
    float4 x = *(const float4*)(xin + (size_t)m * CC + kv);
    __nv_bfloat16 h0 = __float2bfloat16_rn(x.x);
    __nv_bfloat16 h1 = __float2bfloat16_rn(x.y);
    __nv_bfloat16 h2 = __float2bfloat16_rn(x.z);
    __nv_bfloat16 h3 = __float2bfloat16_rn(x.w);
    __nv_bfloat16 l0 = __float2bfloat16_rn(x.x - __bfloat162float(h0));
    __nv_bfloat16 l1 = __float2bfloat16_rn(x.y - __bfloat162float(h1));
    __nv_bfloat16 l2 = __float2bfloat16_rn(x.z - __bfloat162float(h2));
    __nv_bfloat16 l3 = __float2bfloat16_rn(x.w - __bfloat162float(h3));
    __nv_bfloat16* p = g_Xs + (size_t)m * KPA + kv;
    *(__nv_bfloat162*)(p)        = __halves2bfloat162(h0, h1);
    *(__nv_bfloat162*)(p + 2)    = __halves2bfloat162(h2, h3);
    *(__nv_bfloat162*)(p + 2048) = __halves2bfloat162(l0, l1);
    *(__nv_bfloat162*)(p + 2050) = __halves2bfloat162(l2, l3);
}

// ---------------------------------------------------------------------------
// Transpose + split weights: Wt[w][n][4096] = [Wh | Wl]
// ---------------------------------------------------------------------------
__global__ __launch_bounds__(256) void splitW_kernel(
    const float* __restrict__ Wq, const float* __restrict__ Wk,
    const float* __restrict__ Wv, const float* __restrict__ Wo)
{
    __shared__ float tile[32][33];
    int w = blockIdx.z;
    const float* W = (w == 0) ? Wq : (w == 1) ? Wk : (w == 2) ? Wv : Wo;
    __nv_bfloat16* out = g_Wt + (size_t)w * CC * KPA;
    int n0 = blockIdx.x * 32, k0 = blockIdx.y * 32;
    int tx = threadIdx.x & 31, ty = threadIdx.x >> 5;
#pragma unroll
    for (int r = 0; r < 4; r++) {
        int k = k0 + ty + r * 8;
        tile[ty + r * 8][tx] = W[(size_t)k * CC + n0 + tx];
    }
    __syncthreads();
#pragma unroll
    for (int r = 0; r < 4; r++) {
        int n = n0 + ty + r * 8;
        int k = k0 + tx;
        float x = tile[tx][ty + r * 8];
        __nv_bfloat16 hi = __float2bfloat16_rn(x);
        __nv_bfloat16 lo = __float2bfloat16_rn(x - __bfloat162float(hi));
        __nv_bfloat16* pr = out + (size_t)n * KPA;
        pr[k] = hi; pr[2048 + k] = lo;
    }
}

// ---------------------------------------------------------------------------
// V transpose+split: g_V fp32 [bh][t][d] -> g_Vth/g_Vtl bf16 [bh][d][t]
// ---------------------------------------------------------------------------
__global__ __launch_bounds__(256) void vtrans_kernel() {
    __shared__ float tile[32][33];
    int bh = blockIdx.z, t0 = blockIdx.x * 32, d0 = blockIdx.y * 32;
    int tx = threadIdx.x & 31, ty = threadIdx.x >> 5;
    const float* src = g_V + (size_t)bh * TS * DD;
#pragma unroll
    for (int r = 0; r < 4; r++)
        tile[ty + r * 8][tx] = src[(size_t)(t0 + ty + r * 8) * DD + d0 + tx];
    __syncthreads();
#pragma unroll
    for (int r = 0; r < 4; r++) {
        int d = d0 + ty + r * 8;
        int t = t0 + tx;
        float v = tile[tx][ty + r * 8];
        __nv_bfloat16 hv = __float2bfloat16_rn(v);
        __nv_bfloat16 lv = __float2bfloat16_rn(v - __bfloat162float(hv));
        size_t off = (size_t)bh * DD * TS + (size_t)d * TS + t;
        g_Vth[off] = hv;
        g_Vtl[off] = lv;
    }
}

// ---------------------------------------------------------------------------
// mma.sync bf16 GEMM, 3-stage cp.async pipeline, 2 CTAs/SM.
// Logical K' = 6144 (3 planes): Ah*Wh + Ah*Wl + Al*Wh via compact [hi|lo] stores.
// mode 0: -> g_Qh/g_Ql (rope*RSQT) ; mode 1: -> g_Kh/g_Kl (rope)
// mode 2: -> g_V fp32 ; mode 3: AO' @ Wo' -> Cout
// ---------------------------------------------------------------------------
#define SM_STAGE 32768                     // A(16KB) + B(16KB)
#define SM_TOTAL (3 * SM_STAGE)

__global__ __launch_bounds__(256, 2) void tc_gemm_kernel(int modeBase, float* __restrict__ Cout)
{
    extern __shared__ char smc[];
    uint32_t sb = smem_u32(smc);
    const int tid = threadIdx.x, wid = tid >> 5, lane = tid & 31;
    const int wm = wid >> 1, wn = wid & 1;
    const int mode = modeBase + (int)blockIdx.z;
    const __nv_bfloat16* A  = (mode == 3) ? g_AOs : g_Xs;
    const __nv_bfloat16* Bp = g_Wt + (size_t)mode * CC * KPA;
    const int bm = blockIdx.y, bn = blockIdx.x;

    const __nv_bfloat16* Arow = A  + (size_t)(bm * 128) * KPA;
    const __nv_bfloat16* Brow = Bp + (size_t)(bn * 128) * KPA;

    const int ldrow = tid >> 3;
    const int ldc16 = tid & 7;
    const uint32_t sw = ((uint32_t)(ldrow * 128 + ldc16 * 16)) ^ ((ldrow & 7) << 4);

    float c[2][8][4];
#pragma unroll
    for (int i = 0; i < 2; i++)
#pragma unroll
        for (int j = 0; j < 8; j++)
#pragma unroll
            for (int q = 0; q < 4; q++) c[i][j][q] = 0.0f;

    // plane remap: chunk c covers k' = c*64 .. +64, all within one plane
    //   A planes: [Xh | Xh | Xl]  -> compact offset: k'<2048 ? k' : k'-2048
    //   B planes: [Wh | Wl | Wh]  -> compact offset: k'<4096 ? k' : k'-4096
#define AOFF(k0) ((k0) < 2048 ? (k0) : (k0) - 2048)
#define BOFF(k0) ((k0) < 4096 ? (k0) : (k0) - 4096)

    // prologue: chunks 0,1 -> stages 0,1
#pragma unroll
    for (int p = 0; p < 2; p++) {
        int k0 = p * 64;
        int ao = AOFF(k0), bo = BOFF(k0);
        uint32_t st = sb + p * SM_STAGE;
#pragma unroll
        for (int it = 0; it < 4; it++) {
            int row = ldrow + it * 32;
            cpa16(st + sw + it * 4096,         Arow + (size_t)row * KPA + ao + ldc16 * 8);
            cpa16(st + 16384 + sw + it * 4096, Brow + (size_t)row * KPA + bo + ldc16 * 8);
        }
        CP_COMMIT();
    }

    const int lh16 = (lane >> 4) * 16;
    const int rowA0 = wm * 32 + (lane & 15);
    const int kbB = ((lane >> 3) & 1) * 16;
    const int rbase = wn * 64 + ((lane >> 4) << 3) + (lane & 7);

    int stage = 0;
    for (int ch = 0; ch < NCHUNK; ch++) {
        CP_WAIT(1);            // chunk ch's group complete (only ch+1 may pend)
        __syncthreads();       // all warps arrived; stage (ch-1)%3 free to refill
        if (ch + 2 < NCHUNK) {
            int k0 = (ch + 2) * 64;
            int ao = AOFF(k0), bo = BOFF(k0);
            int ns = stage + 2; if (ns >= 3) ns -= 3;
            uint32_t st = sb + ns * SM_STAGE;
#pragma unroll
            for (int it = 0; it < 4; it++) {
                int row = ldrow + it * 32;
                cpa16(st + sw + it * 4096,         Arow + (size_t)row * KPA + ao + ldc16 * 8);
                cpa16(st + 16384 + sw + it * 4096, Brow + (size_t)row * KPA + bo + ldc16 * 8);
            }
        }
        CP_COMMIT();           // uniform group accounting (may be empty)

        uint32_t sbA = sb + stage * SM_STAGE;
        uint32_t sbB = sbA + 16384;
#pragma unroll
        for (int ks = 0; ks < 4; ks++) {
            uint32_t a[2][4], b[4][4];
#pragma unroll
            for (int i = 0; i < 2; i++) {
                int row = rowA0 + i * 16;
                uint32_t kb = ks * 32 + lh16;
                ldsm4(a[i], sbA + row * 128 + (kb ^ ((row & 7) << 4)));
            }
#pragma unroll
            for (int g = 0; g < 4; g++) {
                int row = rbase + g * 16;
                uint32_t kb = ks * 32 + kbB;
                ldsm4(b[g], sbB + row * 128 + (kb ^ ((row & 7) << 4)));
            }
#pragma unroll
            for (int i = 0; i < 2; i++)
#pragma unroll
                for (int j = 0; j < 8; j++)
                    mma16816(c[i][j], a[i], &b[j >> 1][(j & 1) * 2]);
        }
        if (++stage == 3) stage = 0;
    }

    // epilogue
    const int m0g = bm * 128 + wm * 32;
    const int n0g = bn * 128 + wn * 64;
    const int rsub = lane >> 2, cb = (lane & 3) * 2;
#pragma unroll
    for (int i = 0; i < 2; i++) {
#pragma unroll
        for (int half = 0; half < 2; half++) {
            int row = m0g + i * 16 + rsub + half * 8;
            if (mode == 3) {
                float* drow = Cout + (size_t)row * CC;
#pragma unroll
                for (int j = 0; j < 8; j++) {
                    int col = n0g + j * 8 + cb;
                    *(float2*)(drow + col) = make_float2(c[i][j][half * 2],
                                                         c[i][j][half * 2 + 1]);
                }
            } else if (mode == 2) {
                int b = row >> 11, t = row & 2047;
#pragma unroll
                for (int j = 0; j < 8; j++) {
                    int col = n0g + j * 8 + cb;
                    int h = col >> 7, d0 = col & 127;
                    float* dst = g_V + ((size_t)(b * HH + h) * TS + t) * DD + d0;
                    *(float2*)dst = make_float2(c[i][j][half * 2], c[i][j][half * 2 + 1]);
                }
            } else {
                int b = row >> 11, t = row & 2047;
                __nv_bfloat16* outH = (mode == 0) ? g_Qh : g_Kh;
                __nv_bfloat16* outL = (mode == 0) ? g_Ql : g_Kl;
                float s = (mode == 0) ? RSQT : 1.0f;
#pragma unroll
                for (int j = 0; j < 8; j++) {
                    int col = n0g + j * 8 + cb;
                    int h = col >> 7, d0 = col & 127;
                    float2 f = *(const float2*)(g_cfac + t * DD + d0);
                    float v0 = c[i][j][half * 2]     * f.x * s;
                    float v1 = c[i][j][half * 2 + 1] * f.y * s;
                    __nv_bfloat16 h0 = __float2bfloat16_rn(v0);
                    __nv_bfloat16 h1 = __float2bfloat16_rn(v1);
                    __nv_bfloat16 l0 = __float2bfloat16_rn(v0 - __bfloat162float(h0));
                    __nv_bfloat16 l1 = __float2bfloat16_rn(v1 - __bfloat162float(h1));
                    size_t off = ((size_t)(b * HH + h) * TS + t) * DD + d0;
                    *(uint32_t*)(outH + off) = bf2u(h0, h1);
                    *(uint32_t*)(outL + off) = bf2u(l0, l1);
                }
            }
        }
    }
}

// ---------------------------------------------------------------------------
// Tensor-core flash attention, split-bf16 (3-term) for S and PV.
// Epilogue writes hi/lo planes of AO directly into g_AOs (fused split).
// ---------------------------------------------------------------------------
#define ATT_SMEM 196608

__global__ __launch_bounds__(256, 1) void attn_kernel(const float* __restrict__ mask)
{
    extern __shared__ char smc[];
    uint32_t sb = smem_u32(smc);
    const int tid = threadIdx.x, wid = tid >> 5, lane = tid & 31;
    const int mblk = blockIdx.x, bh = blockIdx.y;
    const int b = bh >> 4, h = bh & 15;

    const uint32_t QH = sb, QL = sb + 32768, KH = sb + 65536, KL = sb + 98304,
                   VH = sb + 131072, VL = sb + 163840;

    const size_t qoff = (size_t)bh * TS * DD + (size_t)mblk * 128 * DD;
    const size_t koff = (size_t)bh * TS * DD;
    const size_t voff = (size_t)bh * DD * TS;

    // Q hi/lo resident load
#pragma unroll
    for (int it = 0; it < 8; it++) {
        int id = it * 256 + tid;
        int r = id >> 4;
        uint32_t kb = (id & 15) * 16;
        cpa16(ASW(QH, r, kb), (const char*)g_Qh + ((qoff + (size_t)r * DD) << 1) + kb);
        cpa16(ASW(QL, r, kb), (const char*)g_Ql + ((qoff + (size_t)r * DD) << 1) + kb);
    }
    CP_COMMIT();

    const int rsub = lane >> 2, cb = (lane & 3) * 2;
    const int q0 = mblk * 128 + wid * 16 + rsub;
    const int kbB = ((lane >> 3) & 1) * 16;
    const int rbB = (lane & 7) + ((lane >> 4) << 3);
    const int raA = wid * 16 + (lane & 15);
    const uint32_t kbA = (lane >> 4) * 16;

    float mr0 = -1e30f, mr1 = -1e30f, lr0 = 0.0f, lr1 = 0.0f;
    float o[16][4];
#pragma unroll
    for (int j = 0; j < 16; j++)
#pragma unroll
        for (int q = 0; q < 4; q++) o[j][q] = 0.0f;

    for (int kt = 0; kt < 16; kt++) {
        __syncthreads();
#pragma unroll
        for (int it = 0; it < 8; it++) {
            int id = it * 256 + tid;
            int r = id >> 4;
            uint32_t kb = (id & 15) * 16;
            size_t ge = koff + (size_t)(kt * 128 + r) * DD;
            cpa16(ASW(KH, r, kb), (const char*)g_Kh + (ge << 1) + kb);
            cpa16(ASW(KL, r, kb), (const char*)g_Kl + (ge << 1) + kb);
        }
        CP_COMMIT();
#pragma unroll
        for (int it = 0; it < 8; it++) {
            int id = it * 256 + tid;
            int r = id >> 4;
            uint32_t kb = (id & 15) * 16;
            size_t ge = voff + (size_t)r * TS + kt * 128;
            cpa16(ASW(VH, r, kb), (const char*)g_Vth + (ge << 1) + kb);
            cpa16(ASW(VL, r, kb), (const char*)g_Vtl + (ge << 1) + kb);
        }
        CP_COMMIT();
        CP_WAIT(1);
        __syncthreads();

        // ---- S = Qh*Kh + Qh*Kl + Ql*Kh ----
        float s[16][4];
#pragma unroll
        for (int j = 0; j < 16; j++)
#pragma unroll
            for (int q = 0; q < 4; q++) s[j][q] = 0.0f;

#pragma unroll
        for (int ks = 0; ks < 8; ks++) {
            uint32_t aH[4], aL[4], bHf[8][4], bLf[8][4];
            uint32_t kba = ks * 32 + kbA;
            ldsm4(aH, ASW(QH, raA, kba));
            ldsm4(aL, ASW(QL, raA, kba));
#pragma unroll
            for (int g = 0; g < 8; g++) {
                int rb = g * 16 + rbB;
                uint32_t kb = ks * 32 + kbB;
                ldsm4(bHf[g], ASW(KH, rb, kb));
                ldsm4(bLf[g], ASW(KL, rb, kb));
            }
#pragma unroll
            for (int j = 0; j < 16; j++) {
                mma16816(s[j], aH, &bHf[j >> 1][(j & 1) * 2]);
                mma16816(s[j], aH, &bLf[j >> 1][(j & 1) * 2]);
                mma16816(s[j], aL, &bHf[j >> 1][(j & 1) * 2]);
            }
        }

        // ---- mask add ----
        const float* mrow0 = mask + ((size_t)b * TS + q0) * TS + (size_t)kt * 128;
        const float* mrow1 = mrow0 + (size_t)8 * TS;
#pragma unroll
        for (int j = 0; j < 16; j++) {
            float2 m0 = *(const float2*)(mrow0 + j * 8 + cb);
            float2 m1 = *(const float2*)(mrow1 + j * 8 + cb);
            s[j][0] += m0.x; s[j][1] += m0.y;
            s[j][2] += m1.x; s[j][3] += m1.y;
        }

        // ---- online softmax ----
        float mt0 = -1e30f, mt1 = -1e30f;
#pragma unroll
        for (int j = 0; j < 16; j++) {
            mt0 = fmaxf(mt0, fmaxf(s[j][0], s[j][1]));
            mt1 = fmaxf(mt1, fmaxf(s[j][2], s[j][3]));
        }
        mt0 = fmaxf(mt0, __shfl_xor_sync(0xffffffffu, mt0, 1));
        mt0 = fmaxf(mt0, __shfl_xor_sync(0xffffffffu, mt0, 2));
        mt1 = fmaxf(mt1, __shfl_xor_sync(0xffffffffu, mt1, 1));
        mt1 = fmaxf(mt1, __shfl_xor_sync(0xffffffffu, mt1, 2));
        float mn0 = fmaxf(mr0, mt0), mn1 = fmaxf(mr1, mt1);
        float al0 = __expf(mr0 - mn0), al1 = __expf(mr1 - mn1);
        mr0 = mn0; mr1 = mn1;
        float rs0 = 0.0f, rs1 = 0.0f;
#pragma unroll
        for (int j = 0; j < 16; j++) {
            s[j][0] = __expf(s[j][0] - mn0); rs0 += s[j][0];
            s[j][1] = __expf(s[j][1] - mn0); rs0 += s[j][1];
            s[j][2] = __expf(s[j][2] - mn1); rs1 += s[j][2];
            s[j][3] = __expf(s[j][3] - mn1); rs1 += s[j][3];
        }
        rs0 += __shfl_xor_sync(0xffffffffu, rs0, 1);
        rs0 += __shfl_xor_sync(0xffffffffu, rs0, 2);
        rs1 += __shfl_xor_sync(0xffffffffu, rs1, 1);
        rs1 += __shfl_xor_sync(0xffffffffu, rs1, 2);
        lr0 = lr0 * al0 + rs0;
        lr1 = lr1 * al1 + rs1;
#pragma unroll
        for (int j = 0; j < 16; j++) {
            o[j][0] *= al0; o[j][1] *= al0;
            o[j][2] *= al1; o[j][3] *= al1;
        }

        CP_WAIT(0);
        __syncthreads();

        // ---- O += Ph*Vh + Ph*Vl + Pl*Vh ----
#pragma unroll
        for (int ks = 0; ks < 8; ks++) {
            uint32_t ah[4], alr[4];
#pragma unroll
            for (int half = 0; half < 2; half++) {
                int j = 2 * ks + half;
                __nv_bfloat16 h0 = __float2bfloat16_rn(s[j][0]);
                __nv_bfloat16 h1 = __float2bfloat16_rn(s[j][1]);
                __nv_bfloat16 h2 = __float2bfloat16_rn(s[j][2]);
                __nv_bfloat16 h3 = __float2bfloat16_rn(s[j][3]);
                ah[half * 2 + 0] = bf2u(h0, h1);
                ah[half * 2 + 1] = bf2u(h2, h3);
                __nv_bfloat16 l0 = __float2bfloat16_rn(s[j][0] - __bfloat162float(h0));
                __nv_bfloat16 l1 = __float2bfloat16_rn(s[j][1] - __bfloat162float(h1));
                __nv_bfloat16 l2 = __float2bfloat16_rn(s[j][2] - __bfloat162float(h2));
                __nv_bfloat16 l3 = __float2bfloat16_rn(s[j][3] - __bfloat162float(h3));
                alr[half * 2 + 0] = bf2u(l0, l1);
                alr[half * 2 + 1] = bf2u(l2, l3);
            }
            uint32_t bHf[8][4], bLf[8][4];
#pragma unroll
            for (int g = 0; g < 8; g++) {
                int rb = g * 16 + rbB;
                uint32_t kb = ks * 32 + kbB;
                ldsm4(bHf[g], ASW(VH, rb, kb));
                ldsm4(bLf[g], ASW(VL, rb, kb));
            }
#pragma unroll
            for (int j = 0; j < 16; j++) {
                mma16816(o[j], ah, &bHf[j >> 1][(j & 1) * 2]);
                mma16816(o[j], ah, &bLf[j >> 1][(j & 1) * 2]);
                mma16816(o[j], alr, &bHf[j >> 1][(j & 1) * 2]);
            }
        }
    }

    // ---- finalize: fused hi/lo split, write g_AOs planes directly ----
    float inv0 = 1.0f / lr0, inv1 = 1.0f / lr1;
    const size_t m0 = (size_t)b * TS + q0;       // AO row for o[..][0,1]
    const size_t m1 = m0 + 8;
    const int colb = h * DD;
#pragma unroll
    for (int j = 0; j < 16; j++) {
        int col = colb + j * 8 + cb;
        float v0 = o[j][0] * inv0, v1 = o[j][1] * inv0;
        float v2 = o[j][2] * inv1, v3 = o[j][3] * inv1;
        __nv_bfloat16 h0 = __float2bfloat16_rn(v0);
        __nv_bfloat16 h1 = __float2bfloat16_rn(v1);
        __nv_bfloat16 h2 = __float2bfloat16_rn(v2);
        __nv_bfloat16 h3 = __float2bfloat16_rn(v3);
        *(uint32_t*)(g_AOs + m0 * KPA + col)        = bf2u(h0, h1);
        *(uint32_t*)(g_AOs + m1 * KPA + col)        = bf2u(h2, h3);
        *(uint32_t*)(g_AOs + m0 * KPA + 2048 + col) = bf2u(
            __float2bfloat16_rn(v0 - __bfloat162float(h0)),
            __float2bfloat16_rn(v1 - __bfloat162float(h1)));
        *(uint32_t*)(g_AOs + m1 * KPA + 2048 + col) = bf2u(
            __float2bfloat16_rn(v2 - __bfloat162float(h2)),
            __float2bfloat16_rn(v3 - __bfloat162float(h3)));
    }
}

// ---------------------------------------------------------------------------
// Launch
// ---------------------------------------------------------------------------
extern "C" void kernel_launch(void* const* d_in, const int* in_sizes, int n_in,
                              void* d_out, int out_size)
{
    const float* X   = (const float*)d_in[0];
    const float* msk = (const float*)d_in[1];
    const float* Wq  = (const float*)d_in[2];
    const float* Wk  = (const float*)d_in[3];
    const float* Wv  = (const float*)d_in[4];
    const float* Wo  = (const float*)d_in[5];
    float* out = (float*)d_out;

    cudaFuncSetAttribute(attn_kernel, cudaFuncAttributeMaxDynamicSharedMemorySize, ATT_SMEM);
    cudaFuncSetAttribute(tc_gemm_kernel, cudaFuncAttributeMaxDynamicSharedMemorySize, SM_TOTAL);

    cfac_kernel<<<TS, DD>>>();
    splitW_kernel<<<dim3(64, 64, 4), 256>>>(Wq, Wk, Wv, Wo);
    split_kernel<<<8192, 256>>>(X);

    // QKV projections (mma.sync, bf16-split epilogues)
    tc_gemm_kernel<<<dim3(16, 32, 3), 256, SM_TOTAL>>>(0, nullptr);

    vtrans_kernel<<<dim3(64, 4, 32), 256>>>();

    attn_kernel<<<dim3(16, 32), 256, ATT_SMEM>>>(msk);

    // output projection (AO split fused into attn epilogue)
    tc_gemm_kernel<<<dim3(16, 32, 1), 256, SM_TOTAL>>>(3, out);
}